// round 1
// baseline (speedup 1.0000x reference)
#include <cuda_runtime.h>

// LSTMClassifier: B=2048, T=256, F=64, H=128.
// Per-batch-row recurrence is independent -> each block owns ROWS batch rows,
// loops all T steps locally. No inter-block sync needed.

#define T_STEPS 256
#define FDIM    64
#define HDIM    128
#define KTOT    192          // F + H
#define GDIM    512          // 4H gate columns
#define ROWS    16           // batch rows per block
#define KT      12           // k-tile staged in smem
#define NTILES  16           // 192 / 12
#define NBLOCKS (2048 / ROWS)

// Packed fused weights: g_Wt[k][4*c + q] = (k<F ? W_ih : W_hh)[q*H + c][k or k-F]
__device__ float g_Wt[KTOT * GDIM];
__device__ float g_b4[GDIM];

__global__ void pack_kernel(const float* __restrict__ Wih,
                            const float* __restrict__ Whh,
                            const float* __restrict__ bih,
                            const float* __restrict__ bhh) {
    int idx = blockIdx.x * blockDim.x + threadIdx.x;
    if (idx < KTOT * GDIM) {
        int k = idx >> 9;          // 0..191
        int j = idx & 511;
        int c = j >> 2, q = j & 3;
        int row = q * HDIM + c;    // original gate row (PyTorch order i,f,g,o)
        g_Wt[idx] = (k < FDIM) ? Wih[row * FDIM + k]
                               : Whh[row * HDIM + (k - FDIM)];
    }
    if (idx < GDIM) {
        int c = idx >> 2, q = idx & 3;
        int row = q * HDIM + c;
        g_b4[idx] = bih[row] + bhh[row];
    }
}

__device__ __forceinline__ float sigm(float x) {
    return 1.0f / (1.0f + __expf(-x));
}
__device__ __forceinline__ float tanh_fast(float x) {
    x = fminf(fmaxf(x, -15.0f), 15.0f);
    float e = __expf(2.0f * x);
    return __fdividef(e - 1.0f, e + 1.0f);
}

__global__ __launch_bounds__(256, 1) void lstm_kernel(
    const float* __restrict__ x,
    const float* __restrict__ W1, const float* __restrict__ b1,
    const float* __restrict__ W2, const float* __restrict__ b2,
    float* __restrict__ out)
{
    // inS[k][r]: k<64 = x features of step t, k>=64 = h (transposed, row-minor)
    __shared__ float inS[KTOT][20];      // stride 20 floats -> 16B-aligned rows
    __shared__ float wS[KT][516];        // k-tile of packed weights, padded
    __shared__ float zS[ROWS][32];

    const int tid = threadIdx.x;
    const int b0  = blockIdx.x * ROWS;
    const int rg  = tid >> 7;            // 0..1 : row group (8 rows each)
    const int c   = tid & 127;           // hidden unit owned by this thread

    const float4 breg = *(const float4*)&g_b4[c * 4];

    float creg[8];
#pragma unroll
    for (int i = 0; i < 8; i++) creg[i] = 0.0f;

    // zero the h region of inS (initial hidden state = 0)
    for (int i = tid; i < HDIM * 20; i += 256)
        inS[FDIM + i / 20][i % 20] = 0.0f;

    const float* xbase = x + (long)b0 * T_STEPS * FDIM;

    for (int t = 0; t < T_STEPS; t++) {
        // ---- load x tile for this step, transposed into inS[k][r] ----
        {
            int r  = tid >> 4;           // 0..15
            int kq = (tid & 15) * 4;     // 0..60
            float4 xv = *(const float4*)&xbase[((long)r * T_STEPS + t) * FDIM + kq];
            inS[kq + 0][r] = xv.x;
            inS[kq + 1][r] = xv.y;
            inS[kq + 2][r] = xv.z;
            inS[kq + 3][r] = xv.w;
        }

        float4 acc[8];
#pragma unroll
        for (int rr = 0; rr < 8; rr++) acc[rr] = breg;

        // ---- gates GEMM: acc[rr][q] = b + sum_k in[r][k] * Wt[k][4c+q] ----
#pragma unroll 1
        for (int tile = 0; tile < NTILES; tile++) {
            const int k0 = tile * KT;
            __syncthreads();             // prev tile consumed (also orders x/h writes)
            // stage 12x512 weight slab: coalesced f4 loads, conflict-free f4 stores
#pragma unroll
            for (int w = 0; w < 6; w++) {
                int fi = tid + w * 256;          // 0..1535
                int kk = fi >> 7;                // 0..11
                int jj = (fi & 127) * 4;         // 0..508
                *(float4*)&wS[kk][jj] =
                    *(const float4*)&g_Wt[(k0 + kk) * GDIM + jj];
            }
            __syncthreads();
#pragma unroll
            for (int kk = 0; kk < KT; kk++) {
                float4 w4 = *(const float4*)&wS[kk][c * 4];
                float4 ha = *(const float4*)&inS[k0 + kk][rg * 8];      // rows 0..3
                float4 hb = *(const float4*)&inS[k0 + kk][rg * 8 + 4];  // rows 4..7
                acc[0].x += ha.x * w4.x; acc[0].y += ha.x * w4.y;
                acc[0].z += ha.x * w4.z; acc[0].w += ha.x * w4.w;
                acc[1].x += ha.y * w4.x; acc[1].y += ha.y * w4.y;
                acc[1].z += ha.y * w4.z; acc[1].w += ha.y * w4.w;
                acc[2].x += ha.z * w4.x; acc[2].y += ha.z * w4.y;
                acc[2].z += ha.z * w4.z; acc[2].w += ha.z * w4.w;
                acc[3].x += ha.w * w4.x; acc[3].y += ha.w * w4.y;
                acc[3].z += ha.w * w4.z; acc[3].w += ha.w * w4.w;
                acc[4].x += hb.x * w4.x; acc[4].y += hb.x * w4.y;
                acc[4].z += hb.x * w4.z; acc[4].w += hb.x * w4.w;
                acc[5].x += hb.y * w4.x; acc[5].y += hb.y * w4.y;
                acc[5].z += hb.y * w4.z; acc[5].w += hb.y * w4.w;
                acc[6].x += hb.z * w4.x; acc[6].y += hb.z * w4.y;
                acc[6].z += hb.z * w4.z; acc[6].w += hb.z * w4.w;
                acc[7].x += hb.w * w4.x; acc[7].y += hb.w * w4.y;
                acc[7].z += hb.w * w4.z; acc[7].w += hb.w * w4.w;
            }
        }
        __syncthreads();                 // all reads of inS done before h rewrite

        // ---- pointwise LSTM cell update; c in regs, h -> smem ----
#pragma unroll
        for (int rr = 0; rr < 8; rr++) {
            float ig = sigm(acc[rr].x);
            float fg = sigm(acc[rr].y);
            float gg = tanh_fast(acc[rr].z);
            float og = sigm(acc[rr].w);
            creg[rr] = fg * creg[rr] + ig * gg;
            inS[FDIM + c][rg * 8 + rr] = og * tanh_fast(creg[rr]);
        }
        // next iter: x-load writes inS[k<64] (disjoint), tile-0 sync publishes h
    }
    __syncthreads();

    // ---- head: Linear(128,32) -> ReLU -> Linear(32,1) -> Sigmoid ----
    {
        int m  = tid & 31;               // 0..31 : hidden unit of layer 1
        int r0 = tid >> 5;               // 0..7
#pragma unroll
        for (int h = 0; h < 2; h++) {
            int r = r0 + h * 8;
            float z = b1[m];
            for (int k = 0; k < HDIM; k++)
                z += inS[FDIM + k][r] * W1[m * HDIM + k];
            zS[r][m] = fmaxf(z, 0.0f);
        }
    }
    __syncthreads();
    if (tid < ROWS) {
        float s = b2[0];
#pragma unroll
        for (int m = 0; m < 32; m++) s += zS[tid][m] * W2[m];
        out[b0 + tid] = sigm(s);
    }
}

extern "C" void kernel_launch(void* const* d_in, const int* in_sizes, int n_in,
                              void* d_out, int out_size) {
    const float* x   = (const float*)d_in[0];
    const float* Wih = (const float*)d_in[1];
    const float* Whh = (const float*)d_in[2];
    const float* bih = (const float*)d_in[3];
    const float* bhh = (const float*)d_in[4];
    const float* W1  = (const float*)d_in[5];
    const float* b1  = (const float*)d_in[6];
    const float* W2  = (const float*)d_in[7];
    const float* b2  = (const float*)d_in[8];
    float* out = (float*)d_out;

    pack_kernel<<<(KTOT * GDIM + 255) / 256, 256>>>(Wih, Whh, bih, bhh);
    lstm_kernel<<<NBLOCKS, 256>>>(x, W1, b1, W2, b2, out);
}